// round 5
// baseline (speedup 1.0000x reference)
#include <cuda_runtime.h>
#include <cuda_fp16.h>

#define B_  16
#define Q_  1000
#define N_  16
#define C_  256
#define H_  100
#define W_  100
#define HW_ 10000
#define NH_ 8
#define D_  32
#define TQ  8
#define MP  20         // queries per proj block
#define AP2 260        // A_sm row pitch in halves

// ---- fused kernel smem offsets (bytes) ----
#define OFF_A    0
#define SZ_A     (TQ*N_*AP2*2)          // 66560 half A[128][260]
#define OFF_TM   (OFF_A + SZ_A)         // 66560 half tm[8][8][256] (t then m)
#define SZ_TM    (TQ*NH_*C_*2)          // 32768
#define OFF_SC   (OFF_TM + SZ_TM)       // 99328 float sc[8][8][16]
#define SZ_SC    (TQ*NH_*N_*4)          // 4096
#define OFF_AT   (OFF_SC + SZ_SC)       // 103424 float at[8][16][8]
#define SZ_AT    (TQ*N_*NH_*4)          // 4096
#define OFF_U    (OFF_AT + SZ_AT)       // 107520 float u[64]
#define SZ_U     (TQ*NH_*4)             // 256
#define OFF_WT   (OFF_U + SZ_U)         // 107776 float4 wt[128]
#define SZ_WT    (TQ*N_*16)             // 2048
#define OFF_OY   (OFF_WT + SZ_WT)       // 109824 int2 oy[128]
#define SZ_OY    (TQ*N_*8)              // 1024
#define OFF_OX   (OFF_OY + SZ_OY)       // 110848 ushort2 ox[128]
#define SZ_OX    (TQ*N_*4)              // 512
#define SMEM_BYTES (OFF_OX + SZ_OX)     // 111360 -> 2 blocks/SM

#define PROJ_SMEM (MP*C_*4 + MP*C_*8)   // 61440

// device scratch
__device__ __half g_xt[B_ * HW_ * C_];        // channels-last fp16 x
__device__ float2 g_wqP[(C_/2) * C_];         // wq packed: [k2][c] = {wq[c][2k2], wq[c][2k2+1]}
__device__ float  g_wvT[C_ * C_];             // wv transposed [k][c]
__device__ __half g_t[(size_t)B_ * Q_ * NH_ * C_];   // t[b,q,h,k]
__device__ float  g_u[(size_t)B_ * Q_ * NH_];        // u[b,q,h]

// ---- f32x2 helpers ----
__device__ __forceinline__ void fma2(unsigned long long &d,
                                     unsigned long long a, unsigned long long b) {
    asm volatile("fma.rn.f32x2 %0, %1, %2, %0;" : "+l"(d) : "l"(a), "l"(b));
}
__device__ __forceinline__ unsigned long long lds_b64(unsigned int addr) {
    unsigned long long r;
    asm volatile("ld.shared.b64 %0, [%1];" : "=l"(r) : "r"(addr));
    return r;
}
__device__ __forceinline__ void lds_v2b64(unsigned int addr,
                                          unsigned long long &a, unsigned long long &b) {
    asm volatile("ld.shared.v2.u64 {%0, %1}, [%2];" : "=l"(a), "=l"(b) : "r"(addr));
}

// ---------------------------------------------------------------------------
// Prologue A: pack wq into k-pair float2 layout [k2][c]
// ---------------------------------------------------------------------------
__global__ void pack_wq_kernel(const float* __restrict__ wq) {
    int k2 = blockIdx.x;          // 0..127
    int c  = threadIdx.x;         // 0..255
    float2 v;
    v.x = wq[(size_t)c * C_ + 2 * k2];
    v.y = wq[(size_t)c * C_ + 2 * k2 + 1];
    g_wqP[k2 * C_ + c] = v;
}

// ---------------------------------------------------------------------------
// Prologue B: transpose wv [c][k] -> g_wvT [k][c]
// ---------------------------------------------------------------------------
__global__ void transpose_wv_kernel(const float* __restrict__ wv) {
    __shared__ float tile[32][33];
    int c0 = blockIdx.x * 32;
    int k0 = blockIdx.y * 32;
    int tx = threadIdx.x, ty = threadIdx.y;   // 32x8
    #pragma unroll
    for (int dy = 0; dy < 32; dy += 8)
        tile[ty + dy][tx] = wv[(size_t)(c0 + ty + dy) * C_ + k0 + tx];
    __syncthreads();
    #pragma unroll
    for (int dy = 0; dy < 32; dy += 8)
        g_wvT[(size_t)(k0 + ty + dy) * C_ + c0 + tx] = tile[tx][ty + dy];
}

// ---------------------------------------------------------------------------
// Prologue C: transpose x [B,C,HW] -> g_xt [B,HW,C] (fp16)
// ---------------------------------------------------------------------------
__global__ void transpose_x_kernel(const float* __restrict__ x) {
    __shared__ float tile[32][33];
    int b  = blockIdx.z;
    int p0 = blockIdx.x * 32;   // HW
    int c0 = blockIdx.y * 32;   // C
    int tx = threadIdx.x, ty = threadIdx.y;   // 32x8
    #pragma unroll
    for (int dy = 0; dy < 32; dy += 8) {
        int c = c0 + ty + dy;
        int p = p0 + tx;
        float v = 0.f;
        if (p < HW_) v = x[(size_t)(b * C_ + c) * HW_ + p];
        tile[ty + dy][tx] = v;
    }
    __syncthreads();
    #pragma unroll
    for (int dy = 0; dy < 32; dy += 8) {
        int p = p0 + ty + dy;
        int c = c0 + tx;
        if (p < HW_)
            g_xt[(size_t)(b * HW_ + p) * C_ + c] = __float2half_rn(tile[tx][ty + dy]);
    }
}

// ---------------------------------------------------------------------------
// Kernel P: projections. qp = q@wqT+bq (f32x2), t = per-head qp@wk (f32x2,
// packed along output k), u = qp_head . bk_head. 256 threads, MP queries.
// ---------------------------------------------------------------------------
__global__ __launch_bounds__(256)
void proj_kernel(const float* __restrict__ q,  const float* __restrict__ bq,
                 const float* __restrict__ wk, const float* __restrict__ bk) {
    extern __shared__ float psm[];
    float*  qb  = psm;                          // [MP][256] fp32
    float2* qp2 = (float2*)(psm + MP * C_);     // [MP][256] duplicated pairs {v,v}

    const int tid = threadIdx.x;
    const int b   = blockIdx.y;
    const int q0  = blockIdx.x * MP;

    for (int idx = tid; idx < MP * C_; idx += 256)
        qb[idx] = q[(size_t)(b * Q_ + q0 + idx / C_) * C_ + (idx % C_)];
    __syncthreads();

    unsigned int qb_s  = (unsigned int)__cvta_generic_to_shared(qb);
    unsigned int qp2_s = (unsigned int)__cvta_generic_to_shared(qp2);

    // ---- qp phase: thread owns c; even/odd-k lanes packed ----
    {
        const int c = tid;
        unsigned long long acc2[MP];
        #pragma unroll
        for (int i = 0; i < MP; i++) acc2[i] = 0ull;
        const unsigned long long* wp = (const unsigned long long*)g_wqP;
        #pragma unroll 2
        for (int k4 = 0; k4 < C_ / 4; k4++) {
            unsigned long long w01 = __ldg(wp + (size_t)(2 * k4) * C_ + c);
            unsigned long long w23 = __ldg(wp + (size_t)(2 * k4 + 1) * C_ + c);
            #pragma unroll
            for (int i = 0; i < MP; i++) {
                unsigned long long q01, q23;
                lds_v2b64(qb_s + (i * C_ + k4 * 4) * 4, q01, q23);
                fma2(acc2[i], q01, w01);
                fma2(acc2[i], q23, w23);
            }
        }
        float bb = __ldg(bq + c);
        #pragma unroll
        for (int i = 0; i < MP; i++) {
            float lo = __uint_as_float((unsigned)acc2[i]);
            float hi = __uint_as_float((unsigned)(acc2[i] >> 32));
            float v  = lo + hi + bb;
            qp2[i * C_ + c] = make_float2(v, v);   // duplicated for t-phase b64 loads
        }
    }
    __syncthreads();

    // ---- t phase: thread owns output k-pair (k2), half the i's ----
    {
        const int k2 = tid & 127;
        const int i0 = (tid >> 7) * (MP / 2);   // 0 or MP/2
        for (int h = 0; h < NH_; h++) {
            unsigned long long acc2[MP / 2];
            #pragma unroll
            for (int ii = 0; ii < MP / 2; ii++) acc2[ii] = 0ull;
            #pragma unroll 2
            for (int dd = 0; dd < D_; dd++) {
                unsigned long long w2 =
                    __ldg((const unsigned long long*)(wk + (size_t)(h * D_ + dd) * C_) + k2);
                #pragma unroll
                for (int ii = 0; ii < MP / 2; ii++) {
                    unsigned long long q2 =
                        lds_b64(qp2_s + ((i0 + ii) * C_ + h * D_ + dd) * 8);
                    fma2(acc2[ii], q2, w2);   // lanes = {t[2k2], t[2k2+1]}
                }
            }
            #pragma unroll
            for (int ii = 0; ii < MP / 2; ii++) {
                float lo = __uint_as_float((unsigned)acc2[ii]);
                float hi = __uint_as_float((unsigned)(acc2[ii] >> 32));
                __half2 hv = __floats2half2_rn(lo, hi);
                *(__half2*)(g_t + ((size_t)(b * Q_ + q0 + i0 + ii) * NH_ + h) * C_
                            + 2 * k2) = hv;
            }
        }
    }

    // ---- u phase ----
    if (tid < MP * NH_) {
        int i = tid / NH_, h = tid % NH_;
        float s = 0.f;
        #pragma unroll
        for (int dd = 0; dd < D_; dd++)
            s += qp2[i * C_ + h * D_ + dd].x * __ldg(bk + h * D_ + dd);
        g_u[(size_t)(b * Q_ + q0 + i) * NH_ + h] = s;
    }
}

// ---------------------------------------------------------------------------
// Kernel F: fused gather + attention + output proj. 512 threads, 2 blocks/SM.
// ---------------------------------------------------------------------------
__global__ __launch_bounds__(512, 2)
void deform_attn_kernel(const float* __restrict__ ref,
                        const float* __restrict__ bv,
                        float* __restrict__ out) {
    extern __shared__ char smc[];
    __half*  A_sm  = (__half*)(smc + OFF_A);
    __half*  tm_sm = (__half*)(smc + OFF_TM);
    float*   sc_sm = (float*)(smc + OFF_SC);
    float*   at_sm = (float*)(smc + OFF_AT);
    float*   u_sm  = (float*)(smc + OFF_U);
    float4*  wt_sm = (float4*)(smc + OFF_WT);
    int2*    oy_sm = (int2*)(smc + OFF_OY);
    ushort2* ox_sm = (ushort2*)(smc + OFF_OX);

    const int tid = threadIdx.x;
    const int b   = blockIdx.y;
    const int gq0 = blockIdx.x * TQ;

    // ---- phase 0: ref precompute (128 thr) + t/u load (all) ----
    if (tid < TQ * N_) {
        int i  = tid >> 4, j = tid & 15;
        int rr = (gq0 + i) * N_ + j;
        int n  = rr / Q_;
        int qq = rr - n * Q_;
        float2 g = __ldg((const float2*)(ref + (size_t)((b * Q_ + qq) * N_ + n) * 2));
        float gx = ((g.x + 1.0f) * (float)W_ - 1.0f) * 0.5f;
        float gy = ((g.y + 1.0f) * (float)H_ - 1.0f) * 0.5f;
        float x0f = floorf(gx), y0f = floorf(gy);
        float fx = gx - x0f, fy = gy - y0f;
        int x0 = (int)x0f, y0 = (int)y0f;
        int x1 = x0 + 1,   y1 = y0 + 1;
        bool vx0 = (x0 >= 0) & (x0 < W_);
        bool vx1 = (x1 >= 0) & (x1 < W_);
        bool vy0 = (y0 >= 0) & (y0 < H_);
        bool vy1 = (y1 >= 0) & (y1 < H_);
        float4 w;
        w.x = (vx0 && vy0) ? (1.f - fx) * (1.f - fy) : 0.f;
        w.y = (vx1 && vy0) ? fx * (1.f - fy)         : 0.f;
        w.z = (vx0 && vy1) ? (1.f - fx) * fy         : 0.f;
        w.w = (vx1 && vy1) ? fx * fy                 : 0.f;
        int x0c = min(max(x0, 0), W_ - 1);
        int x1c = min(max(x1, 0), W_ - 1);
        int y0c = min(max(y0, 0), H_ - 1);
        int y1c = min(max(y1, 0), H_ - 1);
        wt_sm[tid] = w;
        oy_sm[tid] = make_int2(y0c * W_ * C_, y1c * W_ * C_);
        ox_sm[tid] = make_ushort2((unsigned short)(x0c * C_),
                                  (unsigned short)(x1c * C_));
    }
    // t load: 16384 halves = 2048 uint4, 4 per thread, coalesced
    {
        const uint4* ts = (const uint4*)(g_t + (size_t)(b * Q_ + gq0) * NH_ * C_);
        uint4* td = (uint4*)tm_sm;
        #pragma unroll
        for (int r = 0; r < 4; r++)
            td[tid + r * 512] = __ldg(ts + tid + r * 512);
    }
    if (tid < TQ * NH_)
        u_sm[tid] = __ldg(g_u + (size_t)(b * Q_ + gq0) * NH_ + tid);
    __syncthreads();

    // ---- gather: all 512 threads, 64 rows each ----
    {
        const int k  = tid & 255;
        const int r0 = tid >> 8;
        const __half* xb = g_xt + (size_t)b * HW_ * C_;
        #pragma unroll 4
        for (int row = r0; row < TQ * N_; row += 2) {
            float4  w  = wt_sm[row];
            int2    oy = oy_sm[row];
            ushort2 ox = ox_sm[row];
            float val =
                w.x * __half2float(__ldg(xb + oy.x + ox.x + k)) +
                w.y * __half2float(__ldg(xb + oy.x + ox.y + k)) +
                w.z * __half2float(__ldg(xb + oy.y + ox.x + k)) +
                w.w * __half2float(__ldg(xb + oy.y + ox.y + k));
            A_sm[row * AP2 + k] = __float2half_rn(val);
        }
    }
    __syncthreads();

    // ---- scores: 512 threads = (i, j, head-pair) ----
    {
        int i  = tid >> 6;
        int j  = (tid >> 2) & 15;
        int hp = (tid & 3) * 2;
        float acc0 = 0.f, acc1 = 0.f;
        const __half2* arow = (const __half2*)(A_sm + (i * N_ + j) * AP2);
        const __half2* t0 = (const __half2*)(tm_sm + (i * NH_ + hp) * C_);
        const __half2* t1 = (const __half2*)(tm_sm + (i * NH_ + hp + 1) * C_);
        #pragma unroll 4
        for (int k4 = 0; k4 < C_ / 4; k4++) {
            float2 a01 = __half22float2(arow[2 * k4]);
            float2 a23 = __half22float2(arow[2 * k4 + 1]);
            float2 u01 = __half22float2(t0[2 * k4]);
            float2 u23 = __half22float2(t0[2 * k4 + 1]);
            float2 v01 = __half22float2(t1[2 * k4]);
            float2 v23 = __half22float2(t1[2 * k4 + 1]);
            acc0 += a01.x * u01.x + a01.y * u01.y + a23.x * u23.x + a23.y * u23.y;
            acc1 += a01.x * v01.x + a01.y * v01.y + a23.x * v23.x + a23.y * v23.y;
        }
        const float scale = 0.17677669529663687f; // 1/sqrt(32)
        sc_sm[(i * NH_ + hp) * N_ + j]     = (acc0 + u_sm[i * NH_ + hp]) * scale;
        sc_sm[(i * NH_ + hp + 1) * N_ + j] = (acc1 + u_sm[i * NH_ + hp + 1]) * scale;
    }
    __syncthreads();

    // ---- softmax over j per (i,h): 64 threads; write attn transposed fp32 ----
    if (tid < TQ * NH_) {
        int i = tid >> 3, h = tid & 7;
        float s[N_];
        float mx = -1e30f;
        #pragma unroll
        for (int j = 0; j < N_; j++) {
            s[j] = sc_sm[(i * NH_ + h) * N_ + j];
            mx = fmaxf(mx, s[j]);
        }
        float sum = 0.f;
        #pragma unroll
        for (int j = 0; j < N_; j++) { s[j] = expf(s[j] - mx); sum += s[j]; }
        float inv = 1.f / sum;
        #pragma unroll
        for (int j = 0; j < N_; j++)
            at_sm[(i * N_ + j) * NH_ + h] = s[j] * inv;
    }
    __syncthreads();

    // ---- m[i][h][k] = sum_j attn*A : 512 threads (k, i-group); overwrite tm ----
    {
        const int k = tid & 255;
        const int g = tid >> 8;
        #pragma unroll
        for (int ii = 0; ii < TQ / 2; ii++) {
            int i = g * (TQ / 2) + ii;
            float acc[NH_];
            #pragma unroll
            for (int h = 0; h < NH_; h++) acc[h] = 0.f;
            #pragma unroll
            for (int j = 0; j < N_; j++) {
                float a = __half2float(A_sm[(i * N_ + j) * AP2 + k]);
                float4 p0 = *(const float4*)(at_sm + (i * N_ + j) * NH_);
                float4 p1 = *(const float4*)(at_sm + (i * N_ + j) * NH_ + 4);
                acc[0] += a * p0.x; acc[1] += a * p0.y;
                acc[2] += a * p0.z; acc[3] += a * p0.w;
                acc[4] += a * p1.x; acc[5] += a * p1.y;
                acc[6] += a * p1.z; acc[7] += a * p1.w;
            }
            #pragma unroll
            for (int h = 0; h < NH_; h++)
                tm_sm[(i * NH_ + h) * C_ + k] = __float2half_rn(acc[h]);
        }
    }
    __syncthreads();

    // ---- out[i][c] = sum_k m[i][h(c)][k]*wvT[k][c] + bv[c] : 512 thr ----
    {
        const int c = tid & 255;
        const int g = tid >> 8;
        const int h = c >> 5;
        float bb = __ldg(bv + c);
        float acc[TQ / 2];
        #pragma unroll
        for (int ii = 0; ii < TQ / 2; ii++) acc[ii] = bb;
        #pragma unroll 2
        for (int k4 = 0; k4 < C_ / 4; k4++) {
            const float* wp = g_wvT + (size_t)(k4 * 4) * C_ + c;
            float w0 = __ldg(wp);
            float w1 = __ldg(wp + C_);
            float w2 = __ldg(wp + 2 * C_);
            float w3 = __ldg(wp + 3 * C_);
            #pragma unroll
            for (int ii = 0; ii < TQ / 2; ii++) {
                int i = g * (TQ / 2) + ii;
                const __half2* mp =
                    (const __half2*)(tm_sm + (i * NH_ + h) * C_ + k4 * 4);
                float2 m01 = __half22float2(mp[0]);
                float2 m23 = __half22float2(mp[1]);
                acc[ii] += m01.x * w0 + m01.y * w1 + m23.x * w2 + m23.y * w3;
            }
        }
        #pragma unroll
        for (int ii = 0; ii < TQ / 2; ii++) {
            int i = g * (TQ / 2) + ii;
            out[(size_t)(b * Q_ + gq0 + i) * C_ + c] = acc[ii];
        }
    }
}

// ---------------------------------------------------------------------------
extern "C" void kernel_launch(void* const* d_in, const int* in_sizes, int n_in,
                              void* d_out, int out_size) {
    const float* x   = (const float*)d_in[0];
    const float* q   = (const float*)d_in[1];
    const float* ref = (const float*)d_in[2];
    const float* wq  = (const float*)d_in[3];
    const float* bq  = (const float*)d_in[4];
    const float* wk  = (const float*)d_in[5];
    const float* bk  = (const float*)d_in[6];
    const float* wv  = (const float*)d_in[7];
    const float* bv  = (const float*)d_in[8];
    float* out = (float*)d_out;

    (void)in_sizes; (void)n_in; (void)out_size;

    pack_wq_kernel<<<C_ / 2, C_>>>(wq);
    transpose_wv_kernel<<<dim3(C_ / 32, C_ / 32), dim3(32, 8)>>>(wv);

    dim3 tg((HW_ + 31) / 32, C_ / 32, B_);
    transpose_x_kernel<<<tg, dim3(32, 8)>>>(x);

    cudaFuncSetAttribute(proj_kernel,
                         cudaFuncAttributeMaxDynamicSharedMemorySize, PROJ_SMEM);
    proj_kernel<<<dim3(Q_ / MP, B_), 256, PROJ_SMEM>>>(q, bq, wk, bk);

    cudaFuncSetAttribute(deform_attn_kernel,
                         cudaFuncAttributeMaxDynamicSharedMemorySize, SMEM_BYTES);
    deform_attn_kernel<<<dim3(Q_ / TQ, B_), 512, SMEM_BYTES>>>(ref, bv, out);
}